// round 7
// baseline (speedup 1.0000x reference)
#include <cuda_runtime.h>
#include <math.h>

// Shapes
#define V_SZ 50257
#define E_SZ 512
#define H_SZ 1024
#define C_SZ 1024
#define S_SZ 2048
#define NRC 16               // row-chunks for wsum partials
#define NBLK 128             // persistent blocks (everything divides evenly)
#define TPB 1024

// ---------------- scratch (device globals) --------------------------------------
__device__ __align__(16) float g_x[H_SZ];               // h of layer 0
__device__ __align__(16) float g_q[H_SZ];               // rnn_output
__device__ __align__(16) float g_u[3][C_SZ];            // W^T q per head
__device__            float g_bq[3];                    // b . q per head
__device__ __align__(16) float g_e[3][S_SZ];            // attention logits
__device__ __align__(16) float g_wpart[3][NRC][C_SZ];   // wsum row-chunk partials
__device__ __align__(16) float g_ctx[3][C_SZ];          // reduced attention contexts
__device__ __align__(16) float g_co[H_SZ];              // concat_out

// ---------------- device-wide barrier (sense-reversal, replay-safe) --------------
__device__ unsigned g_barc;
__device__ volatile unsigned g_barg;

__device__ __forceinline__ void gbar() {
    __syncthreads();
    if (threadIdx.x == 0) {
        __threadfence();
        unsigned gen = g_barg;
        if (atomicAdd(&g_barc, 1u) == NBLK - 1) {
            atomicExch(&g_barc, 0u);
            __threadfence();
            g_barg = gen + 1;
        } else {
            while (g_barg == gen) { __nanosleep(64); }
        }
        __threadfence();
    }
    __syncthreads();
}

// ---------------- helpers --------------------------------------------------------
__device__ __forceinline__ float warp_sum(float v) {
#pragma unroll
    for (int o = 16; o; o >>= 1) v += __shfl_xor_sync(0xffffffffu, v, o);
    return v;
}
__device__ __forceinline__ float warp_max(float v) {
#pragma unroll
    for (int o = 16; o; o >>= 1) v = fmaxf(v, __shfl_xor_sync(0xffffffffu, v, o));
    return v;
}
__device__ __forceinline__ float sigf(float x) { return 1.0f / (1.0f + expf(-x)); }
__device__ __forceinline__ float dot4(float4 w, float4 v) {
    return w.x * v.x + w.y * v.y + w.z * v.z + w.w * v.w;
}

// ==================================================================================
__global__ __launch_bounds__(TPB, 1) void megakernel(
    const int* __restrict__ idx,
    const float* __restrict__ h0,  const float* __restrict__ c0,
    const float* __restrict__ ctxL, const float* __restrict__ ctxR,
    const float* __restrict__ ctxM, const float* __restrict__ emb,
    const float* __restrict__ Wih0, const float* __restrict__ Whh0,
    const float* __restrict__ bih0, const float* __restrict__ bhh0,
    const float* __restrict__ Wih1, const float* __restrict__ Whh1,
    const float* __restrict__ bih1, const float* __restrict__ bhh1,
    const float* __restrict__ WL, const float* __restrict__ bL,
    const float* __restrict__ WR, const float* __restrict__ bR,
    const float* __restrict__ WM, const float* __restrict__ bM,
    const float* __restrict__ Wc, const float* __restrict__ bc,
    const float* __restrict__ Wo, const float* __restrict__ bo,
    float* __restrict__ out, float* __restrict__ h_new, float* __restrict__ c_new)
{
    __shared__ __align__(16) float sm[5200];
    const int tid  = threadIdx.x;
    const int wid  = tid >> 5;
    const int lane = tid & 31;
    const int bid  = blockIdx.x;
    const int gw   = bid * 32 + wid;

    // ============ P1: LSTM layer 0 gates + activation (8 j per block) ============
    {
        const float* x = emb + (size_t)idx[0] * E_SZ;
        for (int i = tid; i < E_SZ; i += TPB) sm[i] = x[i];
        for (int i = tid; i < H_SZ; i += TPB) sm[E_SZ + i] = h0[i];
        __syncthreads();

        const int gi = wid >> 3, jj = wid & 7;
        const int j = bid * 8 + jj;
        const int row = gi * H_SZ + j;
        const float4* a  = (const float4*)(Wih0 + (size_t)row * E_SZ);
        const float4* b  = (const float4*)(Whh0 + (size_t)row * H_SZ);
        const float4* x4 = (const float4*)sm;
        const float4* h4 = (const float4*)(sm + E_SZ);

        float s = 0.f;
        {
            float4 wv[4];
#pragma unroll
            for (int k = 0; k < 4; k++) wv[k] = a[lane + 32 * k];
#pragma unroll
            for (int k = 0; k < 4; k++) s += dot4(wv[k], x4[lane + 32 * k]);
        }
        {
            float4 wv[8];
#pragma unroll
            for (int k = 0; k < 8; k++) wv[k] = b[lane + 32 * k];
#pragma unroll
            for (int k = 0; k < 8; k++) s += dot4(wv[k], h4[lane + 32 * k]);
        }
        s = warp_sum(s);
        if (lane == 0) sm[1536 + gi * 8 + jj] = s + bih0[row] + bhh0[row];
        __syncthreads();

        if (tid < 8) {
            const int jo = bid * 8 + tid;
            const float ig = sigf (sm[1536 + tid]);
            const float fg = sigf (sm[1536 + 8 + tid]);
            const float gg = tanhf(sm[1536 + 16 + tid]);
            const float og = sigf (sm[1536 + 24 + tid]);
            const float c = fg * c0[jo] + ig * gg;
            const float h = og * tanhf(c);
            c_new[jo] = c;
            h_new[jo] = h;
            g_x[jo]  = h;
        }
    }
    gbar();

    // ============ P2: LSTM layer 1 gates + activation, writes q ==================
    {
        for (int i = tid; i < H_SZ; i += TPB) sm[i] = g_x[i];
        for (int i = tid; i < H_SZ; i += TPB) sm[H_SZ + i] = h0[H_SZ + i];
        __syncthreads();

        const int gi = wid >> 3, jj = wid & 7;
        const int j = bid * 8 + jj;
        const int row = gi * H_SZ + j;
        const float4* a  = (const float4*)(Wih1 + (size_t)row * H_SZ);
        const float4* b  = (const float4*)(Whh1 + (size_t)row * H_SZ);
        const float4* x4 = (const float4*)sm;
        const float4* h4 = (const float4*)(sm + H_SZ);

        float s = 0.f;
        {
            float4 wv[8];
#pragma unroll
            for (int k = 0; k < 8; k++) wv[k] = a[lane + 32 * k];
#pragma unroll
            for (int k = 0; k < 8; k++) s += dot4(wv[k], x4[lane + 32 * k]);
        }
        {
            float4 wv[8];
#pragma unroll
            for (int k = 0; k < 8; k++) wv[k] = b[lane + 32 * k];
#pragma unroll
            for (int k = 0; k < 8; k++) s += dot4(wv[k], h4[lane + 32 * k]);
        }
        s = warp_sum(s);
        if (lane == 0) sm[2048 + gi * 8 + jj] = s + bih1[row] + bhh1[row];
        __syncthreads();

        if (tid < 8) {
            const int jo = bid * 8 + tid;
            const float ig = sigf (sm[2048 + tid]);
            const float fg = sigf (sm[2048 + 8 + tid]);
            const float gg = tanhf(sm[2048 + 16 + tid]);
            const float og = sigf (sm[2048 + 24 + tid]);
            const float c = fg * c0[H_SZ + jo] + ig * gg;
            const float h = og * tanhf(c);
            c_new[H_SZ + jo] = c;
            h_new[H_SZ + jo] = h;
            g_q[jo] = h;
        }
    }
    gbar();

    // ============ P3: u = W^T q (+ bq) — 3 units/block, perfectly balanced =======
    {
        for (int i = tid; i < H_SZ; i += TPB) sm[i] = g_q[i];
        __syncthreads();
        const int col  = tid & 1;            // 2 f4 cols per unit
        const int rgrp = tid >> 1;           // 0..511
        float4* red = (float4*)(sm + 1024);  // 1024 float4

#pragma unroll
        for (int t = 0; t < 3; t++) {
            const int hd = t;
            const float* W    = (hd == 0) ? WL : (hd == 1) ? WR : WM;
            const float* bias = (hd == 0) ? bL : (hd == 1) ? bR : bM;
            const int c4 = bid * 2 + col;    // f4 column (0..255)
            const float4* W4 = (const float4*)W;

            float4 w0 = W4[(size_t)rgrp * (C_SZ >> 2) + c4];
            float4 w1 = W4[(size_t)(rgrp + 512) * (C_SZ >> 2) + c4];
            const float q0 = sm[rgrp], q1 = sm[rgrp + 512];
            float4 acc;
            acc.x = w0.x * q0 + w1.x * q1;
            acc.y = w0.y * q0 + w1.y * q1;
            acc.z = w0.z * q0 + w1.z * q1;
            acc.w = w0.w * q0 + w1.w * q1;
            red[rgrp * 2 + col] = acc;
            __syncthreads();
#pragma unroll
            for (int sd = 256; sd >= 1; sd >>= 1) {
                if (rgrp < sd) {
                    float4 o = red[(rgrp + sd) * 2 + col];
                    float4 m = red[rgrp * 2 + col];
                    m.x += o.x; m.y += o.y; m.z += o.z; m.w += o.w;
                    red[rgrp * 2 + col] = m;
                }
                __syncthreads();
            }
            if (tid < 2) ((float4*)g_u[hd])[bid * 2 + tid] = red[tid];

            if (bid == 0) {   // bq = bias . q, fixed-order
                float v = bias[tid] * sm[tid];
                v = warp_sum(v);
                if (lane == 0) sm[5120 + wid] = v;
                __syncthreads();
                if (tid < 32) {
                    float tt = sm[5120 + tid];
                    tt = warp_sum(tt);
                    if (tid == 0) g_bq[hd] = tt;
                }
            }
            __syncthreads();
        }
    }
    gbar();

    // ============ P4: e[hd][s] = ctx[s,:]·u[hd] + bq[hd] =========================
    {
        for (int i = tid; i < 3 * C_SZ; i += TPB) sm[i] = ((const float*)g_u)[i];
        __syncthreads();
        for (int r = gw; r < 3 * S_SZ; r += NBLK * 32) {
            const int hd = r >> 11, srow = r & (S_SZ - 1);
            const float* ctx = (hd == 0) ? ctxL : (hd == 1) ? ctxR : ctxM;
            const float4* c4 = (const float4*)(ctx + (size_t)srow * C_SZ);
            const float4* u4 = (const float4*)(sm + hd * C_SZ);
            float4 wv[8];
#pragma unroll
            for (int k = 0; k < 8; k++) wv[k] = c4[lane + 32 * k];
            float s = 0.f;
#pragma unroll
            for (int k = 0; k < 8; k++) s += dot4(wv[k], u4[lane + 32 * k]);
            s = warp_sum(s);
            if (lane == 0) g_e[hd][srow] = s + g_bq[hd];
        }
    }
    gbar();

    // ============ P5: softmax + weighted column-sum partials (3 units/block) =====
    {
        const int cc = bid & 7;          // col chunk (32 f4)
        const int rc = bid >> 3;         // row chunk (128 rows), 16 chunks
        float4* red4 = (float4*)(sm + 256);
#pragma unroll
        for (int t = 0; t < 3; t++) {
            const int hd = t;
            // softmax stats over full 2048 logits (deterministic)
            const float e0 = g_e[hd][tid], e1 = g_e[hd][tid + 1024];
            float m = warp_max(fmaxf(e0, e1));
            if (lane == 0) sm[130 + wid] = m;
            __syncthreads();
            if (tid < 32) {
                float v = sm[130 + tid];
                v = warp_max(v);
                if (tid == 0) sm[164] = v;
            }
            __syncthreads();
            const float M = sm[164];
            float z = expf(e0 - M) + expf(e1 - M);
            z = warp_sum(z);
            __syncthreads();
            if (lane == 0) sm[130 + wid] = z;
            __syncthreads();
            if (tid < 32) {
                float v = sm[130 + tid];
                v = warp_sum(v);
                if (tid == 0) sm[165] = v;
            }
            __syncthreads();
            const float inv = 1.0f / sm[165];
            if (tid < 128) sm[tid] = expf(g_e[hd][rc * 128 + tid] - M) * inv;
            __syncthreads();

            // weighted column sum over 128 rows x 128 floats (L2-warm from P4)
            const float* ctx = (hd == 0) ? ctxL : (hd == 1) ? ctxR : ctxM;
            const float4* cp = (const float4*)ctx;
            const int c4col = cc * 32 + lane;
            float4 v[4];
#pragma unroll
            for (int k = 0; k < 4; k++)
                v[k] = cp[(size_t)(rc * 128 + wid + 32 * k) * (C_SZ >> 2) + c4col];
            float4 acc = make_float4(0.f, 0.f, 0.f, 0.f);
#pragma unroll
            for (int k = 0; k < 4; k++) {
                float av = sm[wid + 32 * k];
                acc.x += v[k].x * av; acc.y += v[k].y * av;
                acc.z += v[k].z * av; acc.w += v[k].w * av;
            }
            red4[wid * 32 + lane] = acc;
            __syncthreads();
#pragma unroll
            for (int sd = 16; sd >= 1; sd >>= 1) {
                if (wid < sd) {
                    float4 o = red4[(wid + sd) * 32 + lane];
                    float4 mm = red4[wid * 32 + lane];
                    mm.x += o.x; mm.y += o.y; mm.z += o.z; mm.w += o.w;
                    red4[wid * 32 + lane] = mm;
                }
                __syncthreads();
            }
            if (wid == 0) ((float4*)g_wpart[hd][rc])[cc * 32 + lane] = red4[lane];
            __syncthreads();
        }
    }
    gbar();

    // ============ P5b: reduce 16 partials -> g_ctx (48 blocks, 64 threads) =======
    if (bid < 48 && tid < 64) {
        const int hd = bid >> 4, seg = bid & 15;
        const int c = seg * 64 + tid;
        float s = 0.f;
#pragma unroll
        for (int k = 0; k < NRC; k++) s += g_wpart[hd][k][c];
        g_ctx[hd][c] = s;
    }
    gbar();

    // ============ P6: concat_out = tanh(Wc @ [q|l|r|m] + bc) =====================
    {
        for (int i = tid; i < 4 * H_SZ; i += TPB)
            sm[i] = (i < H_SZ) ? g_q[i] : g_ctx[(i >> 10) - 1][i & (H_SZ - 1)];
        __syncthreads();

        const int row = bid * 8 + (wid >> 2);      // 8 rows/block, 4 warps/row
        const int seg = wid & 3;
        const float4* a  = (const float4*)(Wc + (size_t)row * 4 * H_SZ + seg * H_SZ);
        const float4* x4 = (const float4*)(sm + seg * H_SZ);
        float4 wv[8];
#pragma unroll
        for (int k = 0; k < 8; k++) wv[k] = a[lane + 32 * k];
        float s = 0.f;
#pragma unroll
        for (int k = 0; k < 8; k++) s += dot4(wv[k], x4[lane + 32 * k]);
        s = warp_sum(s);
        if (lane == 0) sm[4096 + (wid >> 2) * 4 + seg] = s;
        __syncthreads();
        if (tid < 8) {
            const float t = sm[4096 + tid * 4] + sm[4096 + tid * 4 + 1] +
                            sm[4096 + tid * 4 + 2] + sm[4096 + tid * 4 + 3];
            const int ro = bid * 8 + tid;
            g_co[ro] = tanhf(t + bc[ro]);
        }
    }
    gbar();

    // ============ P7: output = Wo @ concat_out + bo (row pairs per warp) =========
    {
        if (tid < H_SZ) sm[tid] = g_co[tid];
        __syncthreads();
        const float4* x4 = (const float4*)sm;
        for (int r = gw; r < V_SZ; r += 2 * NBLK * 32) {
            const int r2 = r + NBLK * 32;
            const bool v2 = r2 < V_SZ;
            const float4* a = (const float4*)(Wo + (size_t)r * H_SZ);
            const float4* b = (const float4*)(Wo + (size_t)(v2 ? r2 : r) * H_SZ);
            float sa = 0.f, sb = 0.f;
            float4 wa[4], wb[4];
            // half 1 (f4 0..127)
#pragma unroll
            for (int k = 0; k < 4; k++) wa[k] = a[lane + 32 * k];
#pragma unroll
            for (int k = 0; k < 4; k++) wb[k] = b[lane + 32 * k];
#pragma unroll
            for (int k = 0; k < 4; k++) sa += dot4(wa[k], x4[lane + 32 * k]);
#pragma unroll
            for (int k = 0; k < 4; k++) sb += dot4(wb[k], x4[lane + 32 * k]);
            // half 2 (f4 128..255)
#pragma unroll
            for (int k = 0; k < 4; k++) wa[k] = a[lane + 32 * (k + 4)];
#pragma unroll
            for (int k = 0; k < 4; k++) wb[k] = b[lane + 32 * (k + 4)];
#pragma unroll
            for (int k = 0; k < 4; k++) sa += dot4(wa[k], x4[lane + 32 * (k + 4)]);
#pragma unroll
            for (int k = 0; k < 4; k++) sb += dot4(wb[k], x4[lane + 32 * (k + 4)]);
            sa = warp_sum(sa);
            sb = warp_sum(sb);
            if (lane == 0) {
                out[r] = sa + bo[r];
                if (v2) out[r2] = sb + bo[r2];
            }
        }
    }
}

// ==================================================================================
extern "C" void kernel_launch(void* const* d_in, const int* in_sizes, int n_in,
                              void* d_out, int out_size) {
    const int*   input_ids = (const int*)  d_in[0];
    const float* h0        = (const float*)d_in[1];
    const float* c0        = (const float*)d_in[2];
    const float* ctxL      = (const float*)d_in[3];
    const float* ctxR      = (const float*)d_in[4];
    const float* ctxM      = (const float*)d_in[5];
    const float* emb       = (const float*)d_in[6];
    const float* Wih0      = (const float*)d_in[7];
    const float* Whh0      = (const float*)d_in[8];
    const float* bih0      = (const float*)d_in[9];
    const float* bhh0      = (const float*)d_in[10];
    const float* Wih1      = (const float*)d_in[11];
    const float* Whh1      = (const float*)d_in[12];
    const float* bih1      = (const float*)d_in[13];
    const float* bhh1      = (const float*)d_in[14];
    const float* WL        = (const float*)d_in[15];
    const float* bL        = (const float*)d_in[16];
    const float* WR        = (const float*)d_in[17];
    const float* bR        = (const float*)d_in[18];
    const float* WM        = (const float*)d_in[19];
    const float* bM        = (const float*)d_in[20];
    const float* Wc        = (const float*)d_in[21];
    const float* bc        = (const float*)d_in[22];
    const float* Wo        = (const float*)d_in[23];
    const float* bo        = (const float*)d_in[24];

    float* out   = (float*)d_out;            // [V]
    float* h_new = out + V_SZ;               // [2*H]
    float* c_new = out + V_SZ + 2 * H_SZ;    // [2*H]

    megakernel<<<NBLK, TPB>>>(input_ids, h0, c0, ctxL, ctxR, ctxM, emb,
                              Wih0, Whh0, bih0, bhh0, Wih1, Whh1, bih1, bhh1,
                              WL, bL, WR, bR, WM, bM, Wc, bc, Wo, bo,
                              out, h_new, c_new);
}

// round 8
// speedup vs baseline: 1.0363x; 1.0363x over previous
#include <cuda_runtime.h>
#include <math.h>

// Shapes
#define V_SZ 50257
#define E_SZ 512
#define H_SZ 1024
#define C_SZ 1024
#define S_SZ 2048
#define NRC 16               // row-chunks for wsum partials
#define NBLK 148             // persistent blocks — one per SM, ALL SMs stream
#define TPB 1024

// ---------------- scratch (device globals) --------------------------------------
__device__ __align__(16) float g_x[H_SZ];               // h of layer 0
__device__ __align__(16) float g_q[H_SZ];               // rnn_output
__device__ __align__(16) float g_u[3][C_SZ];            // W^T q per head
__device__            float g_bq[3];                    // b . q per head
__device__ __align__(16) float g_e[3][S_SZ];            // attention logits
__device__ __align__(16) float g_wpart[3][NRC][C_SZ];   // wsum row-chunk partials
__device__ __align__(16) float g_ctx[3][C_SZ];          // reduced attention contexts
__device__ __align__(16) float g_co[H_SZ];              // concat_out

// ---------------- device-wide barrier (sense-reversal, replay-safe) --------------
__device__ unsigned g_barc;
__device__ volatile unsigned g_barg;

__device__ __forceinline__ void gbar() {
    __syncthreads();
    if (threadIdx.x == 0) {
        __threadfence();
        unsigned gen = g_barg;
        if (atomicAdd(&g_barc, 1u) == NBLK - 1) {
            atomicExch(&g_barc, 0u);
            __threadfence();
            g_barg = gen + 1;
        } else {
            while (g_barg == gen) { __nanosleep(64); }
        }
        __threadfence();
    }
    __syncthreads();
}

// ---------------- helpers --------------------------------------------------------
__device__ __forceinline__ float warp_sum(float v) {
#pragma unroll
    for (int o = 16; o; o >>= 1) v += __shfl_xor_sync(0xffffffffu, v, o);
    return v;
}
__device__ __forceinline__ float warp_max(float v) {
#pragma unroll
    for (int o = 16; o; o >>= 1) v = fmaxf(v, __shfl_xor_sync(0xffffffffu, v, o));
    return v;
}
__device__ __forceinline__ float sigf(float x) { return 1.0f / (1.0f + expf(-x)); }
__device__ __forceinline__ float dot4(float4 w, float4 v) {
    return w.x * v.x + w.y * v.y + w.z * v.z + w.w * v.w;
}

// ==================================================================================
__global__ __launch_bounds__(TPB, 1) void megakernel(
    const int* __restrict__ idx,
    const float* __restrict__ h0,  const float* __restrict__ c0,
    const float* __restrict__ ctxL, const float* __restrict__ ctxR,
    const float* __restrict__ ctxM, const float* __restrict__ emb,
    const float* __restrict__ Wih0, const float* __restrict__ Whh0,
    const float* __restrict__ bih0, const float* __restrict__ bhh0,
    const float* __restrict__ Wih1, const float* __restrict__ Whh1,
    const float* __restrict__ bih1, const float* __restrict__ bhh1,
    const float* __restrict__ WL, const float* __restrict__ bL,
    const float* __restrict__ WR, const float* __restrict__ bR,
    const float* __restrict__ WM, const float* __restrict__ bM,
    const float* __restrict__ Wc, const float* __restrict__ bc,
    const float* __restrict__ Wo, const float* __restrict__ bo,
    float* __restrict__ out, float* __restrict__ h_new, float* __restrict__ c_new)
{
    __shared__ __align__(16) float sm[5200];
    const int tid  = threadIdx.x;
    const int wid  = tid >> 5;
    const int lane = tid & 31;
    const int bid  = blockIdx.x;
    const int gw   = bid * 32 + wid;

    // ============ P1: LSTM layer 0 gates + activation (all 148 blocks) ===========
    {
        const float* x = emb + (size_t)idx[0] * E_SZ;
        for (int i = tid; i < E_SZ; i += TPB) sm[i] = x[i];
        for (int i = tid; i < H_SZ; i += TPB) sm[E_SZ + i] = h0[i];
        __syncthreads();

        const int gi = wid >> 3, jj = wid & 7;     // jj 0..7, slot 7 idle
        const int j = bid + 148 * jj;
        if (jj < 7 && j < H_SZ) {
            const int row = gi * H_SZ + j;
            const float4* a  = (const float4*)(Wih0 + (size_t)row * E_SZ);
            const float4* b  = (const float4*)(Whh0 + (size_t)row * H_SZ);
            const float4* x4 = (const float4*)sm;
            const float4* h4 = (const float4*)(sm + E_SZ);
            float s = 0.f;
            {
                float4 wv[4];
#pragma unroll
                for (int k = 0; k < 4; k++) wv[k] = __ldcs(a + lane + 32 * k);
#pragma unroll
                for (int k = 0; k < 4; k++) s += dot4(wv[k], x4[lane + 32 * k]);
            }
            {
                float4 wv[8];
#pragma unroll
                for (int k = 0; k < 8; k++) wv[k] = __ldcs(b + lane + 32 * k);
#pragma unroll
                for (int k = 0; k < 8; k++) s += dot4(wv[k], h4[lane + 32 * k]);
            }
            s = warp_sum(s);
            if (lane == 0) sm[1536 + gi * 8 + jj] = s + bih0[row] + bhh0[row];
        }
        __syncthreads();

        if (tid < 7) {
            const int jo = bid + 148 * tid;
            if (jo < H_SZ) {
                const float ig = sigf (sm[1536 + tid]);
                const float fg = sigf (sm[1536 + 8 + tid]);
                const float gg = tanhf(sm[1536 + 16 + tid]);
                const float og = sigf (sm[1536 + 24 + tid]);
                const float c = fg * c0[jo] + ig * gg;
                const float h = og * tanhf(c);
                c_new[jo] = c;
                h_new[jo] = h;
                g_x[jo]  = h;
            }
        }
    }
    gbar();

    // ============ P2: LSTM layer 1 gates + activation, writes q ==================
    {
        for (int i = tid; i < H_SZ; i += TPB) sm[i] = g_x[i];
        for (int i = tid; i < H_SZ; i += TPB) sm[H_SZ + i] = h0[H_SZ + i];
        __syncthreads();

        const int gi = wid >> 3, jj = wid & 7;
        const int j = bid + 148 * jj;
        if (jj < 7 && j < H_SZ) {
            const int row = gi * H_SZ + j;
            const float4* a  = (const float4*)(Wih1 + (size_t)row * H_SZ);
            const float4* b  = (const float4*)(Whh1 + (size_t)row * H_SZ);
            const float4* x4 = (const float4*)sm;
            const float4* h4 = (const float4*)(sm + H_SZ);
            float s = 0.f;
            {
                float4 wv[8];
#pragma unroll
                for (int k = 0; k < 8; k++) wv[k] = __ldcs(a + lane + 32 * k);
#pragma unroll
                for (int k = 0; k < 8; k++) s += dot4(wv[k], x4[lane + 32 * k]);
            }
            {
                float4 wv[8];
#pragma unroll
                for (int k = 0; k < 8; k++) wv[k] = __ldcs(b + lane + 32 * k);
#pragma unroll
                for (int k = 0; k < 8; k++) s += dot4(wv[k], h4[lane + 32 * k]);
            }
            s = warp_sum(s);
            if (lane == 0) sm[2048 + gi * 8 + jj] = s + bih1[row] + bhh1[row];
        }
        __syncthreads();

        if (tid < 7) {
            const int jo = bid + 148 * tid;
            if (jo < H_SZ) {
                const float ig = sigf (sm[2048 + tid]);
                const float fg = sigf (sm[2048 + 8 + tid]);
                const float gg = tanhf(sm[2048 + 16 + tid]);
                const float og = sigf (sm[2048 + 24 + tid]);
                const float c = fg * c0[H_SZ + jo] + ig * gg;
                const float h = og * tanhf(c);
                c_new[H_SZ + jo] = c;
                h_new[H_SZ + jo] = h;
                g_q[jo] = h;
            }
        }
    }
    gbar();

    // ============ P3: u = W^T q (+ bq) — 384 fine units over 148 blocks ==========
    {
        for (int i = tid; i < H_SZ; i += TPB) sm[i] = g_q[i];
        __syncthreads();
        const int col  = tid & 1;            // 2 f4 cols per unit
        const int rgrp = tid >> 1;           // 0..511
        float4* red = (float4*)(sm + 1024);  // 1024 float4

        for (int vb = bid; vb < 384; vb += NBLK) {
            const int hd = vb >> 7, chunk = vb & 127;
            const float* W    = (hd == 0) ? WL : (hd == 1) ? WR : WM;
            const float* bias = (hd == 0) ? bL : (hd == 1) ? bR : bM;
            const int c4 = chunk * 2 + col;  // f4 column (0..255)
            const float4* W4 = (const float4*)W;

            float4 w0 = __ldcs(W4 + (size_t)rgrp * (C_SZ >> 2) + c4);
            float4 w1 = __ldcs(W4 + (size_t)(rgrp + 512) * (C_SZ >> 2) + c4);
            const float q0 = sm[rgrp], q1 = sm[rgrp + 512];
            float4 acc;
            acc.x = w0.x * q0 + w1.x * q1;
            acc.y = w0.y * q0 + w1.y * q1;
            acc.z = w0.z * q0 + w1.z * q1;
            acc.w = w0.w * q0 + w1.w * q1;
            red[rgrp * 2 + col] = acc;
            __syncthreads();
#pragma unroll
            for (int sd = 256; sd >= 1; sd >>= 1) {
                if (rgrp < sd) {
                    float4 o = red[(rgrp + sd) * 2 + col];
                    float4 m = red[rgrp * 2 + col];
                    m.x += o.x; m.y += o.y; m.z += o.z; m.w += o.w;
                    red[rgrp * 2 + col] = m;
                }
                __syncthreads();
            }
            if (tid < 2) ((float4*)g_u[hd])[chunk * 2 + tid] = red[tid];

            if (chunk == 0) {   // bq = bias . q, fixed-order
                float v = bias[tid] * sm[tid];
                v = warp_sum(v);
                if (lane == 0) sm[5120 + wid] = v;
                __syncthreads();
                if (tid < 32) {
                    float tt = sm[5120 + tid];
                    tt = warp_sum(tt);
                    if (tid == 0) g_bq[hd] = tt;
                }
            }
            __syncthreads();
        }
    }
    gbar();

    // ============ P4: e[hd][s] = ctx[s,:]·u[hd] + bq[hd] (interleaved) ===========
    {
        for (int i = tid; i < 3 * C_SZ; i += TPB) sm[i] = ((const float*)g_u)[i];
        __syncthreads();
        const int r0 = bid + 148 * wid;     // 0..4735, unique per warp
#pragma unroll
        for (int it = 0; it < 2; it++) {
            const int r = r0 + it * 4736;
            if (r < 3 * S_SZ) {
                const int hd = r >> 11, srow = r & (S_SZ - 1);
                const float* ctx = (hd == 0) ? ctxL : (hd == 1) ? ctxR : ctxM;
                const float4* c4 = (const float4*)(ctx + (size_t)srow * C_SZ);
                const float4* u4 = (const float4*)(sm + hd * C_SZ);
                float4 wv[8];
#pragma unroll
                for (int k = 0; k < 8; k++) wv[k] = c4[lane + 32 * k];
                float s = 0.f;
#pragma unroll
                for (int k = 0; k < 8; k++) s += dot4(wv[k], u4[lane + 32 * k]);
                s = warp_sum(s);
                if (lane == 0) g_e[hd][srow] = s + g_bq[hd];
            }
        }
    }
    gbar();

    // ============ P5: softmax + weighted column-sum partials =====================
    {
        // stats once per block for all 3 heads (deterministic fixed order)
#pragma unroll
        for (int hd = 0; hd < 3; hd++) {
            const float e0 = g_e[hd][tid], e1 = g_e[hd][tid + 1024];
            float m = warp_max(fmaxf(e0, e1));
            if (lane == 0) sm[130 + wid] = m;
            __syncthreads();
            if (tid < 32) {
                float v = sm[130 + tid];
                v = warp_max(v);
                if (tid == 0) sm[164] = v;
            }
            __syncthreads();
            const float M = sm[164];
            float z = expf(e0 - M) + expf(e1 - M);
            z = warp_sum(z);
            __syncthreads();
            if (lane == 0) sm[130 + wid] = z;
            __syncthreads();
            if (tid < 32) {
                float v = sm[130 + tid];
                v = warp_sum(v);
                if (tid == 0) { sm[168 + hd] = M; sm[172 + hd] = 1.0f / v; }
            }
            __syncthreads();
        }

        float4* red4 = (float4*)(sm + 256);
        for (int vb = bid; vb < 384; vb += NBLK) {
            const int hd = vb >> 7, t = vb & 127;
            const int rc = t >> 3, cc = t & 7;
            const float M = sm[168 + hd], inv = sm[172 + hd];
            if (tid < 128) sm[tid] = expf(g_e[hd][rc * 128 + tid] - M) * inv;
            __syncthreads();

            const float* ctx = (hd == 0) ? ctxL : (hd == 1) ? ctxR : ctxM;
            const float4* cp = (const float4*)ctx;
            const int c4col = cc * 32 + lane;
            float4 v[4];
#pragma unroll
            for (int k = 0; k < 4; k++)
                v[k] = __ldcs(cp + (size_t)(rc * 128 + wid + 32 * k) * (C_SZ >> 2) + c4col);
            float4 acc = make_float4(0.f, 0.f, 0.f, 0.f);
#pragma unroll
            for (int k = 0; k < 4; k++) {
                float av = sm[wid + 32 * k];
                acc.x += v[k].x * av; acc.y += v[k].y * av;
                acc.z += v[k].z * av; acc.w += v[k].w * av;
            }
            red4[wid * 32 + lane] = acc;
            __syncthreads();
#pragma unroll
            for (int sd = 16; sd >= 1; sd >>= 1) {
                if (wid < sd) {
                    float4 o = red4[(wid + sd) * 32 + lane];
                    float4 mm = red4[wid * 32 + lane];
                    mm.x += o.x; mm.y += o.y; mm.z += o.z; mm.w += o.w;
                    red4[wid * 32 + lane] = mm;
                }
                __syncthreads();
            }
            if (wid == 0) ((float4*)g_wpart[hd][rc])[cc * 32 + lane] = red4[lane];
            __syncthreads();
        }
    }
    gbar();

    // ============ P5b: reduce 16 partials -> g_ctx ===============================
    if (bid < 48 && tid < 64) {
        const int hd = bid >> 4, seg = bid & 15;
        const int c = seg * 64 + tid;
        float s = 0.f;
#pragma unroll
        for (int k = 0; k < NRC; k++) s += g_wpart[hd][k][c];
        g_ctx[hd][c] = s;
    }
    gbar();

    // ============ P6: concat_out = tanh(Wc @ [q|l|r|m] + bc), all blocks =========
    {
        for (int i = tid; i < 4 * H_SZ; i += TPB)
            sm[i] = (i < H_SZ) ? g_q[i] : g_ctx[(i >> 10) - 1][i & (H_SZ - 1)];
        __syncthreads();

        const int rs = wid >> 2, seg = wid & 3;    // row slot 0..7, 4 warps/row
        const int row = bid + 148 * rs;
        if (row < H_SZ) {
            const float4* a  = (const float4*)(Wc + (size_t)row * 4 * H_SZ + seg * H_SZ);
            const float4* x4 = (const float4*)(sm + seg * H_SZ);
            float4 wv[8];
#pragma unroll
            for (int k = 0; k < 8; k++) wv[k] = __ldcs(a + lane + 32 * k);
            float s = 0.f;
#pragma unroll
            for (int k = 0; k < 8; k++) s += dot4(wv[k], x4[lane + 32 * k]);
            s = warp_sum(s);
            if (lane == 0) sm[4200 + rs * 4 + seg] = s;
        }
        __syncthreads();
        if (tid < 7) {
            const int ro = bid + 148 * tid;
            if (ro < H_SZ) {
                const float t = sm[4200 + tid * 4] + sm[4200 + tid * 4 + 1] +
                                sm[4200 + tid * 4 + 2] + sm[4200 + tid * 4 + 3];
                g_co[ro] = tanhf(t + bc[ro]);
            }
        }
    }
    gbar();

    // ============ P7: output = Wo @ concat_out + bo (row pairs per warp) =========
    {
        if (tid < H_SZ) sm[tid] = g_co[tid];
        __syncthreads();
        const float4* x4 = (const float4*)sm;
        for (int r = gw; r < V_SZ; r += 2 * NBLK * 32) {
            const int r2 = r + NBLK * 32;
            const bool v2 = r2 < V_SZ;
            const float4* a = (const float4*)(Wo + (size_t)r * H_SZ);
            const float4* b = (const float4*)(Wo + (size_t)(v2 ? r2 : r) * H_SZ);
            float sa = 0.f, sb = 0.f;
            float4 wa[4], wb[4];
#pragma unroll
            for (int k = 0; k < 4; k++) wa[k] = __ldcs(a + lane + 32 * k);
#pragma unroll
            for (int k = 0; k < 4; k++) wb[k] = __ldcs(b + lane + 32 * k);
#pragma unroll
            for (int k = 0; k < 4; k++) sa += dot4(wa[k], x4[lane + 32 * k]);
#pragma unroll
            for (int k = 0; k < 4; k++) sb += dot4(wb[k], x4[lane + 32 * k]);
#pragma unroll
            for (int k = 0; k < 4; k++) wa[k] = __ldcs(a + lane + 32 * (k + 4));
#pragma unroll
            for (int k = 0; k < 4; k++) wb[k] = __ldcs(b + lane + 32 * (k + 4));
#pragma unroll
            for (int k = 0; k < 4; k++) sa += dot4(wa[k], x4[lane + 32 * (k + 4)]);
#pragma unroll
            for (int k = 0; k < 4; k++) sb += dot4(wb[k], x4[lane + 32 * (k + 4)]);
            sa = warp_sum(sa);
            sb = warp_sum(sb);
            if (lane == 0) {
                out[r] = sa + bo[r];
                if (v2) out[r2] = sb + bo[r2];
            }
        }
    }
}

// ==================================================================================
extern "C" void kernel_launch(void* const* d_in, const int* in_sizes, int n_in,
                              void* d_out, int out_size) {
    const int*   input_ids = (const int*)  d_in[0];
    const float* h0        = (const float*)d_in[1];
    const float* c0        = (const float*)d_in[2];
    const float* ctxL      = (const float*)d_in[3];
    const float* ctxR      = (const float*)d_in[4];
    const float* ctxM      = (const float*)d_in[5];
    const float* emb       = (const float*)d_in[6];
    const float* Wih0      = (const float*)d_in[7];
    const float* Whh0      = (const float*)d_in[8];
    const float* bih0      = (const float*)d_in[9];
    const float* bhh0      = (const float*)d_in[10];
    const float* Wih1      = (const float*)d_in[11];
    const float* Whh1      = (const float*)d_in[12];
    const float* bih1      = (const float*)d_in[13];
    const float* bhh1      = (const float*)d_in[14];
    const float* WL        = (const float*)d_in[15];
    const float* bL        = (const float*)d_in[16];
    const float* WR        = (const float*)d_in[17];
    const float* bR        = (const float*)d_in[18];
    const float* WM        = (const float*)d_in[19];
    const float* bM        = (const float*)d_in[20];
    const float* Wc        = (const float*)d_in[21];
    const float* bc        = (const float*)d_in[22];
    const float* Wo        = (const float*)d_in[23];
    const float* bo        = (const float*)d_in[24];

    float* out   = (float*)d_out;            // [V]
    float* h_new = out + V_SZ;               // [2*H]
    float* c_new = out + V_SZ + 2 * H_SZ;    // [2*H]

    megakernel<<<NBLK, TPB>>>(input_ids, h0, c0, ctxL, ctxR, ctxM, emb,
                              Wih0, Whh0, bih0, bhh0, Wih1, Whh1, bih1, bhh1,
                              WL, bL, WR, bR, WM, bM, Wc, bc, Wo, bo,
                              out, h_new, c_new);
}

// round 9
// speedup vs baseline: 1.0773x; 1.0396x over previous
#include <cuda_runtime.h>
#include <math.h>

// Shapes
#define V_SZ 50257
#define E_SZ 512
#define H_SZ 1024
#define C_SZ 1024
#define S_SZ 2048
#define NRC 8                // row-chunks for wsum partials
#define NBLK 148             // persistent blocks (1 per SM)
#define TPB 1024

// ---------------- scratch (device globals) --------------------------------------
__device__ __align__(16) float g_x[H_SZ];               // h of layer 0
__device__ __align__(16) float g_q[H_SZ];               // rnn_output
__device__ __align__(16) float g_u[3][C_SZ];            // W^T q per head
__device__            float g_bq[3];                    // b . q per head
__device__ __align__(16) float g_e[3][S_SZ];            // attention logits
__device__ __align__(16) float g_wpart[3][NRC][C_SZ];   // wsum row-chunk partials
__device__ __align__(16) float g_ctx[3][C_SZ];          // reduced attention contexts
__device__ __align__(16) float g_co[H_SZ];              // concat_out

// ---------------- device-wide barrier (sense-reversal, replay-safe) --------------
__device__ unsigned g_barc;
__device__ volatile unsigned g_barg;

__device__ __forceinline__ void gbar() {
    __syncthreads();
    if (threadIdx.x == 0) {
        __threadfence();
        unsigned gen = g_barg;
        if (atomicAdd(&g_barc, 1u) == NBLK - 1) {
            atomicExch(&g_barc, 0u);
            __threadfence();
            g_barg = gen + 1;
        } else {
            while (g_barg == gen) { __nanosleep(64); }
        }
        __threadfence();
    }
    __syncthreads();
}

// ---------------- helpers --------------------------------------------------------
__device__ __forceinline__ float warp_sum(float v) {
#pragma unroll
    for (int o = 16; o; o >>= 1) v += __shfl_xor_sync(0xffffffffu, v, o);
    return v;
}
__device__ __forceinline__ float warp_max(float v) {
#pragma unroll
    for (int o = 16; o; o >>= 1) v = fmaxf(v, __shfl_xor_sync(0xffffffffu, v, o));
    return v;
}
__device__ __forceinline__ float sigf(float x) { return 1.0f / (1.0f + expf(-x)); }
__device__ __forceinline__ float dot4(float4 w, float4 v) {
    return w.x * v.x + w.y * v.y + w.z * v.z + w.w * v.w;
}

// ==================================================================================
__global__ __launch_bounds__(TPB, 1) void megakernel(
    const int* __restrict__ idx,
    const float* __restrict__ h0,  const float* __restrict__ c0,
    const float* __restrict__ ctxL, const float* __restrict__ ctxR,
    const float* __restrict__ ctxM, const float* __restrict__ emb,
    const float* __restrict__ Wih0, const float* __restrict__ Whh0,
    const float* __restrict__ bih0, const float* __restrict__ bhh0,
    const float* __restrict__ Wih1, const float* __restrict__ Whh1,
    const float* __restrict__ bih1, const float* __restrict__ bhh1,
    const float* __restrict__ WL, const float* __restrict__ bL,
    const float* __restrict__ WR, const float* __restrict__ bR,
    const float* __restrict__ WM, const float* __restrict__ bM,
    const float* __restrict__ Wc, const float* __restrict__ bc,
    const float* __restrict__ Wo, const float* __restrict__ bo,
    float* __restrict__ out, float* __restrict__ h_new, float* __restrict__ c_new)
{
    __shared__ __align__(16) float sm[5200];
    const int tid  = threadIdx.x;
    const int wid  = tid >> 5;
    const int lane = tid & 31;
    const int bid  = blockIdx.x;
    const int gw   = bid * 32 + wid;

    // ============ P1: LSTM layer 0 gates + activation (all 148 blocks) ===========
    {
        const float* x = emb + (size_t)idx[0] * E_SZ;
        for (int i = tid; i < E_SZ; i += TPB) sm[i] = x[i];
        for (int i = tid; i < H_SZ; i += TPB) sm[E_SZ + i] = h0[i];
        __syncthreads();

        const int gi = wid >> 3, jj = wid & 7;       // jj 0..7, slot 7 idle
        const int j = bid + 148 * jj;
        if (jj < 7 && j < H_SZ) {
            const int row = gi * H_SZ + j;
            const float4* a  = (const float4*)(Wih0 + (size_t)row * E_SZ);
            const float4* b  = (const float4*)(Whh0 + (size_t)row * H_SZ);
            const float4* x4 = (const float4*)sm;
            const float4* h4 = (const float4*)(sm + E_SZ);

            float s = 0.f;
            {
                float4 wv[4];
#pragma unroll
                for (int k = 0; k < 4; k++) wv[k] = a[lane + 32 * k];
#pragma unroll
                for (int k = 0; k < 4; k++) s += dot4(wv[k], x4[lane + 32 * k]);
            }
            {
                float4 wv[8];
#pragma unroll
                for (int k = 0; k < 8; k++) wv[k] = b[lane + 32 * k];
#pragma unroll
                for (int k = 0; k < 8; k++) s += dot4(wv[k], h4[lane + 32 * k]);
            }
            s = warp_sum(s);
            if (lane == 0) sm[1536 + gi * 8 + jj] = s + bih0[row] + bhh0[row];
        }
        __syncthreads();

        if (tid < 7) {
            const int jo = bid + 148 * tid;
            if (jo < H_SZ) {
                const float ig = sigf (sm[1536 + tid]);
                const float fg = sigf (sm[1536 + 8 + tid]);
                const float gg = tanhf(sm[1536 + 16 + tid]);
                const float og = sigf (sm[1536 + 24 + tid]);
                const float c = fg * c0[jo] + ig * gg;
                const float h = og * tanhf(c);
                c_new[jo] = c;
                h_new[jo] = h;
                g_x[jo]  = h;
            }
        }
    }
    gbar();

    // ============ P2: LSTM layer 1 gates + activation, writes q ==================
    {
        for (int i = tid; i < H_SZ; i += TPB) sm[i] = g_x[i];
        for (int i = tid; i < H_SZ; i += TPB) sm[H_SZ + i] = h0[H_SZ + i];
        __syncthreads();

        const int gi = wid >> 3, jj = wid & 7;
        const int j = bid + 148 * jj;
        if (jj < 7 && j < H_SZ) {
            const int row = gi * H_SZ + j;
            const float4* a  = (const float4*)(Wih1 + (size_t)row * H_SZ);
            const float4* b  = (const float4*)(Whh1 + (size_t)row * H_SZ);
            const float4* x4 = (const float4*)sm;
            const float4* h4 = (const float4*)(sm + H_SZ);

            float s = 0.f;
            {
                float4 wv[8];
#pragma unroll
                for (int k = 0; k < 8; k++) wv[k] = a[lane + 32 * k];
#pragma unroll
                for (int k = 0; k < 8; k++) s += dot4(wv[k], x4[lane + 32 * k]);
            }
            {
                float4 wv[8];
#pragma unroll
                for (int k = 0; k < 8; k++) wv[k] = b[lane + 32 * k];
#pragma unroll
                for (int k = 0; k < 8; k++) s += dot4(wv[k], h4[lane + 32 * k]);
            }
            s = warp_sum(s);
            if (lane == 0) sm[2048 + gi * 8 + jj] = s + bih1[row] + bhh1[row];
        }
        __syncthreads();

        if (tid < 7) {
            const int jo = bid + 148 * tid;
            if (jo < H_SZ) {
                const float ig = sigf (sm[2048 + tid]);
                const float fg = sigf (sm[2048 + 8 + tid]);
                const float gg = tanhf(sm[2048 + 16 + tid]);
                const float og = sigf (sm[2048 + 24 + tid]);
                const float c = fg * c0[H_SZ + jo] + ig * gg;
                const float h = og * tanhf(c);
                c_new[H_SZ + jo] = c;
                h_new[H_SZ + jo] = h;
                g_q[jo] = h;
            }
        }
    }
    gbar();

    // ============ P3: u = W^T q (+ bq) — 192 virtual blocks (as in R6) ===========
    for (int i = tid; i < H_SZ; i += TPB) sm[i] = g_q[i];
    __syncthreads();
    for (int vb = bid; vb < 192; vb += NBLK) {
        const int hd = vb >> 6, chunk = vb & 63;
        const float* W    = (hd == 0) ? WL : (hd == 1) ? WR : WM;
        const float* bias = (hd == 0) ? bL : (hd == 1) ? bR : bM;
        const int col = tid & 3, rgrp = tid >> 2;        // 4 f4 cols, 256 rowgroups
        const int c4 = chunk * 4 + col;
        const float4* W4 = (const float4*)W;

        float4 wv[4];
#pragma unroll
        for (int k = 0; k < 4; k++)
            wv[k] = W4[(size_t)(rgrp + 256 * k) * (C_SZ >> 2) + c4];
        float4 acc = make_float4(0.f, 0.f, 0.f, 0.f);
#pragma unroll
        for (int k = 0; k < 4; k++) {
            float qv = sm[rgrp + 256 * k];
            acc.x += wv[k].x * qv; acc.y += wv[k].y * qv;
            acc.z += wv[k].z * qv; acc.w += wv[k].w * qv;
        }
        float4* red = (float4*)(sm + H_SZ);              // 1024 float4
        red[rgrp * 4 + col] = acc;
        __syncthreads();
#pragma unroll
        for (int sd = 128; sd >= 1; sd >>= 1) {
            if (rgrp < sd) {
                float4 o = red[(rgrp + sd) * 4 + col];
                float4 m = red[rgrp * 4 + col];
                m.x += o.x; m.y += o.y; m.z += o.z; m.w += o.w;
                red[rgrp * 4 + col] = m;
            }
            __syncthreads();
        }
        if (tid < 4) ((float4*)g_u[hd])[chunk * 4 + tid] = red[tid];

        if (chunk == 0) {   // bq = bias . q, fixed-order
            float v = bias[tid] * sm[tid];
            v = warp_sum(v);
            if (lane == 0) sm[5120 + wid] = v;
            __syncthreads();
            if (tid < 32) {
                float t = sm[5120 + tid];
                t = warp_sum(t);
                if (tid == 0) g_bq[hd] = t;
            }
        }
        __syncthreads();
    }
    gbar();

    // ============ P4: e[hd][s] = ctx[s,:]·u[hd] + bq[hd] (as in R6) ==============
    for (int i = tid; i < 3 * C_SZ; i += TPB) sm[i] = ((const float*)g_u)[i];
    __syncthreads();
    for (int r = gw; r < 3 * S_SZ; r += NBLK * 32) {
        const int hd = r >> 11, srow = r & (S_SZ - 1);
        const float* ctx = (hd == 0) ? ctxL : (hd == 1) ? ctxR : ctxM;
        const float4* c4 = (const float4*)(ctx + (size_t)srow * C_SZ);
        const float4* u4 = (const float4*)(sm + hd * C_SZ);
        float4 wv[8];
#pragma unroll
        for (int k = 0; k < 8; k++) wv[k] = c4[lane + 32 * k];
        float s = 0.f;
#pragma unroll
        for (int k = 0; k < 8; k++) s += dot4(wv[k], u4[lane + 32 * k]);
        s = warp_sum(s);
        if (lane == 0) g_e[hd][srow] = s + g_bq[hd];
    }
    gbar();

    // ============ P5: softmax + weighted column-sum partials (as in R6) ==========
    for (int vb = bid; vb < 192; vb += NBLK) {
        const int cc = vb & 7, rc = (vb >> 3) & 7, hd = vb >> 6;
        // softmax stats over full 2048 logits (deterministic)
        const float e0 = g_e[hd][tid], e1 = g_e[hd][tid + 1024];
        float m = warp_max(fmaxf(e0, e1));
        if (lane == 0) sm[4608 + wid] = m;
        __syncthreads();
        if (tid < 32) {
            float v = sm[4608 + tid];
            v = warp_max(v);
            if (tid == 0) sm[4700] = v;
        }
        __syncthreads();
        const float M = sm[4700];
        float z = expf(e0 - M) + expf(e1 - M);
        z = warp_sum(z);
        __syncthreads();
        if (lane == 0) sm[4608 + wid] = z;
        __syncthreads();
        if (tid < 32) {
            float v = sm[4608 + tid];
            v = warp_sum(v);
            if (tid == 0) sm[4701] = v;
        }
        __syncthreads();
        const float inv = 1.0f / sm[4701];
        if (tid < 256) sm[4096 + tid] = expf(g_e[hd][rc * 256 + tid] - M) * inv;
        __syncthreads();

        // weighted column sum over 256 rows (L2-warm from P4)
        const float* ctx = (hd == 0) ? ctxL : (hd == 1) ? ctxR : ctxM;
        const float4* cp = (const float4*)ctx;
        const int c4col = cc * 32 + lane;
        float4 v[8];
#pragma unroll
        for (int k = 0; k < 8; k++)
            v[k] = cp[(size_t)(rc * 256 + wid + 32 * k) * (C_SZ >> 2) + c4col];
        float4 acc = make_float4(0.f, 0.f, 0.f, 0.f);
#pragma unroll
        for (int k = 0; k < 8; k++) {
            float av = sm[4096 + wid + 32 * k];
            acc.x += v[k].x * av; acc.y += v[k].y * av;
            acc.z += v[k].z * av; acc.w += v[k].w * av;
        }
        float4* red4 = (float4*)sm;
        red4[wid * 32 + lane] = acc;
        __syncthreads();
#pragma unroll
        for (int sd = 16; sd >= 1; sd >>= 1) {
            if (wid < sd) {
                float4 o = red4[(wid + sd) * 32 + lane];
                float4 mm = red4[wid * 32 + lane];
                mm.x += o.x; mm.y += o.y; mm.z += o.z; mm.w += o.w;
                red4[wid * 32 + lane] = mm;
            }
            __syncthreads();
        }
        if (wid == 0) ((float4*)g_wpart[hd][rc])[cc * 32 + lane] = red4[lane];
        __syncthreads();
    }
    gbar();

    // ============ P5b: reduce 8 partials -> g_ctx ================================
    if (bid < 48 && tid < 64) {
        const int hd = bid >> 4, seg = bid & 15;
        const int c = seg * 64 + tid;
        float s = 0.f;
#pragma unroll
        for (int k = 0; k < NRC; k++) s += g_wpart[hd][k][c];
        g_ctx[hd][c] = s;
    }
    gbar();

    // ============ P6: concat_out = tanh(Wc @ [q|l|r|m] + bc), all 148 blocks =====
    {
        for (int i = tid; i < 4 * H_SZ; i += TPB)
            sm[i] = (i < H_SZ) ? g_q[i] : g_ctx[(i >> 10) - 1][i & (H_SZ - 1)];
        __syncthreads();

        const int rs = wid >> 2, seg = wid & 3;    // row slot 0..7 (7 used), 4 warps/row
        const int row = bid + 148 * rs;
        if (rs < 7 && row < H_SZ) {
            const float4* a  = (const float4*)(Wc + (size_t)row * 4 * H_SZ + seg * H_SZ);
            const float4* x4 = (const float4*)(sm + seg * H_SZ);
            float4 wv[8];
#pragma unroll
            for (int k = 0; k < 8; k++) wv[k] = a[lane + 32 * k];
            float s = 0.f;
#pragma unroll
            for (int k = 0; k < 8; k++) s += dot4(wv[k], x4[lane + 32 * k]);
            s = warp_sum(s);
            if (lane == 0) sm[4200 + rs * 4 + seg] = s;
        }
        __syncthreads();
        if (tid < 7) {
            const int ro = bid + 148 * tid;
            if (ro < H_SZ) {
                const float t = sm[4200 + tid * 4] + sm[4200 + tid * 4 + 1] +
                                sm[4200 + tid * 4 + 2] + sm[4200 + tid * 4 + 3];
                g_co[ro] = tanhf(t + bc[ro]);
            }
        }
    }
    gbar();

    // ============ P7: output = Wo @ concat_out + bo (as in R6, single row) =======
    if (tid < H_SZ) sm[tid] = g_co[tid];
    __syncthreads();
    const float4* x4 = (const float4*)sm;
    for (int r = gw; r < V_SZ; r += NBLK * 32) {
        const float4* a = (const float4*)(Wo + (size_t)r * H_SZ);
        float4 wv[8];
#pragma unroll
        for (int k = 0; k < 8; k++) wv[k] = a[lane + 32 * k];
        float s = 0.f;
#pragma unroll
        for (int k = 0; k < 8; k++) s += dot4(wv[k], x4[lane + 32 * k]);
        s = warp_sum(s);
        if (lane == 0) out[r] = s + bo[r];
    }
}

// ==================================================================================
extern "C" void kernel_launch(void* const* d_in, const int* in_sizes, int n_in,
                              void* d_out, int out_size) {
    const int*   input_ids = (const int*)  d_in[0];
    const float* h0        = (const float*)d_in[1];
    const float* c0        = (const float*)d_in[2];
    const float* ctxL      = (const float*)d_in[3];
    const float* ctxR      = (const float*)d_in[4];
    const float* ctxM      = (const float*)d_in[5];
    const float* emb       = (const float*)d_in[6];
    const float* Wih0      = (const float*)d_in[7];
    const float* Whh0      = (const float*)d_in[8];
    const float* bih0      = (const float*)d_in[9];
    const float* bhh0      = (const float*)d_in[10];
    const float* Wih1      = (const float*)d_in[11];
    const float* Whh1      = (const float*)d_in[12];
    const float* bih1      = (const float*)d_in[13];
    const float* bhh1      = (const float*)d_in[14];
    const float* WL        = (const float*)d_in[15];
    const float* bL        = (const float*)d_in[16];
    const float* WR        = (const float*)d_in[17];
    const float* bR        = (const float*)d_in[18];
    const float* WM        = (const float*)d_in[19];
    const float* bM        = (const float*)d_in[20];
    const float* Wc        = (const float*)d_in[21];
    const float* bc        = (const float*)d_in[22];
    const float* Wo        = (const float*)d_in[23];
    const float* bo        = (const float*)d_in[24];

    float* out   = (float*)d_out;            // [V]
    float* h_new = out + V_SZ;               // [2*H]
    float* c_new = out + V_SZ + 2 * H_SZ;    // [2*H]

    megakernel<<<NBLK, TPB>>>(input_ids, h0, c0, ctxL, ctxR, ctxM, emb,
                              Wih0, Whh0, bih0, bhh0, Wih1, Whh1, bih1, bhh1,
                              WL, bL, WR, bR, WM, bM, Wc, bc, Wo, bo,
                              out, h_new, c_new);
}

// round 10
// speedup vs baseline: 1.0978x; 1.0190x over previous
#include <cuda_runtime.h>
#include <math.h>

// Shapes
#define V_SZ 50257
#define E_SZ 512
#define H_SZ 1024
#define C_SZ 1024
#define S_SZ 2048
#define NRC 8                // row-chunks for wsum partials
#define NBLK 148             // persistent blocks (1 per SM, single wave)
#define TPB 1024
#define PF_LINES 4096        // 512 KB of W_out prefetched per block (max)

// ---------------- scratch (device globals) --------------------------------------
__device__ __align__(16) float g_x[H_SZ];               // h of layer 0
__device__ __align__(16) float g_q[H_SZ];               // rnn_output
__device__ __align__(16) float g_u[3][C_SZ];            // W^T q per head
__device__            float g_bq[3];                    // b . q per head
__device__ __align__(16) float g_e[3][S_SZ];            // attention logits
__device__ __align__(16) float g_wpart[3][NRC][C_SZ];   // wsum row-chunk partials
__device__ __align__(16) float g_co[H_SZ];              // concat_out

// ---------------- device-wide barrier with prefetch-while-waiting ----------------
__device__ unsigned g_barc;
__device__ volatile unsigned g_barg;

// While waiting for the barrier release, warp 1 prefetches this block's slice of
// W_out into L2 (evict_last), throttled so stragglers' demand loads aren't starved.
__device__ __forceinline__ void gbar_pf(const char* pf_base, int& pf_i) {
    __shared__ int s_rel;
    __syncthreads();
    if (threadIdx.x == 0) s_rel = 0;
    __syncthreads();
    const int tid = threadIdx.x;
    if (tid == 0) {
        __threadfence();
        unsigned gen = g_barg;
        if (atomicAdd(&g_barc, 1u) == NBLK - 1) {
            atomicExch(&g_barc, 0u);
            __threadfence();
            g_barg = gen + 1;
        } else {
            while (g_barg == gen) { __nanosleep(64); }
        }
        __threadfence();
        *(volatile int*)&s_rel = 1;
    } else if (tid >= 32 && tid < 64) {
        const int ln = tid - 32;
        while (*(volatile int*)&s_rel == 0) {
            if (pf_i < PF_LINES) {
                const char* p = pf_base + (size_t)(pf_i + ln) * 128;
#pragma unroll
                for (int k = 0; k < 4; k++)
                    asm volatile("prefetch.global.L2::evict_last [%0];" :: "l"(p + k * 4096));
                pf_i += 128;          // 128 lines (16 KB) per iteration
            }
            __nanosleep(256);
        }
    }
    __syncthreads();
}

// ---------------- helpers --------------------------------------------------------
__device__ __forceinline__ float warp_sum(float v) {
#pragma unroll
    for (int o = 16; o; o >>= 1) v += __shfl_xor_sync(0xffffffffu, v, o);
    return v;
}
__device__ __forceinline__ float warp_max(float v) {
#pragma unroll
    for (int o = 16; o; o >>= 1) v = fmaxf(v, __shfl_xor_sync(0xffffffffu, v, o));
    return v;
}
__device__ __forceinline__ float sigf(float x) { return 1.0f / (1.0f + expf(-x)); }
__device__ __forceinline__ float dot4(float4 w, float4 v) {
    return w.x * v.x + w.y * v.y + w.z * v.z + w.w * v.w;
}

// ==================================================================================
__global__ __launch_bounds__(TPB, 1) void megakernel(
    const int* __restrict__ idx,
    const float* __restrict__ h0,  const float* __restrict__ c0,
    const float* __restrict__ ctxL, const float* __restrict__ ctxR,
    const float* __restrict__ ctxM, const float* __restrict__ emb,
    const float* __restrict__ Wih0, const float* __restrict__ Whh0,
    const float* __restrict__ bih0, const float* __restrict__ bhh0,
    const float* __restrict__ Wih1, const float* __restrict__ Whh1,
    const float* __restrict__ bih1, const float* __restrict__ bhh1,
    const float* __restrict__ WL, const float* __restrict__ bL,
    const float* __restrict__ WR, const float* __restrict__ bR,
    const float* __restrict__ WM, const float* __restrict__ bM,
    const float* __restrict__ Wc, const float* __restrict__ bc,
    const float* __restrict__ Wo, const float* __restrict__ bo,
    float* __restrict__ out, float* __restrict__ h_new, float* __restrict__ c_new)
{
    __shared__ __align__(16) float sm[5200];
    const int tid  = threadIdx.x;
    const int wid  = tid >> 5;
    const int lane = tid & 31;
    const int bid  = blockIdx.x;
    const int gw   = bid * 32 + wid;

    // per-block prefetch slice of W_out (148 * 512KB = 77.6MB of 206MB)
    const char* pf_base = (const char*)Wo + (size_t)bid * PF_LINES * 128;
    int pf_i = 0;

    // ============ P1: LSTM layer 0 gates + activation (blocks 0..127) ============
    if (bid < 128) {
        const float* x = emb + (size_t)idx[0] * E_SZ;
        for (int i = tid; i < E_SZ; i += TPB) sm[i] = x[i];
        for (int i = tid; i < H_SZ; i += TPB) sm[E_SZ + i] = h0[i];
        __syncthreads();

        const int gi = wid >> 3, jj = wid & 7;
        const int j = bid * 8 + jj;
        const int row = gi * H_SZ + j;
        const float4* a  = (const float4*)(Wih0 + (size_t)row * E_SZ);
        const float4* b  = (const float4*)(Whh0 + (size_t)row * H_SZ);
        const float4* x4 = (const float4*)sm;
        const float4* h4 = (const float4*)(sm + E_SZ);

        float s = 0.f;
        {
            float4 wv[4];
#pragma unroll
            for (int k = 0; k < 4; k++) wv[k] = a[lane + 32 * k];
#pragma unroll
            for (int k = 0; k < 4; k++) s += dot4(wv[k], x4[lane + 32 * k]);
        }
        {
            float4 wv[8];
#pragma unroll
            for (int k = 0; k < 8; k++) wv[k] = b[lane + 32 * k];
#pragma unroll
            for (int k = 0; k < 8; k++) s += dot4(wv[k], h4[lane + 32 * k]);
        }
        s = warp_sum(s);
        if (lane == 0) sm[1536 + gi * 8 + jj] = s + bih0[row] + bhh0[row];
        __syncthreads();

        if (tid < 8) {
            const int jo = bid * 8 + tid;
            const float ig = sigf (sm[1536 + tid]);
            const float fg = sigf (sm[1536 + 8 + tid]);
            const float gg = tanhf(sm[1536 + 16 + tid]);
            const float og = sigf (sm[1536 + 24 + tid]);
            const float c = fg * c0[jo] + ig * gg;
            const float h = og * tanhf(c);
            c_new[jo] = c;
            h_new[jo] = h;
            g_x[jo]  = h;
        }
    }
    gbar_pf(pf_base, pf_i);

    // ============ P2: LSTM layer 1 gates + activation, writes q ==================
    if (bid < 128) {
        for (int i = tid; i < H_SZ; i += TPB) sm[i] = g_x[i];
        for (int i = tid; i < H_SZ; i += TPB) sm[H_SZ + i] = h0[H_SZ + i];
        __syncthreads();

        const int gi = wid >> 3, jj = wid & 7;
        const int j = bid * 8 + jj;
        const int row = gi * H_SZ + j;
        const float4* a  = (const float4*)(Wih1 + (size_t)row * H_SZ);
        const float4* b  = (const float4*)(Whh1 + (size_t)row * H_SZ);
        const float4* x4 = (const float4*)sm;
        const float4* h4 = (const float4*)(sm + H_SZ);

        float s = 0.f;
        {
            float4 wv[8];
#pragma unroll
            for (int k = 0; k < 8; k++) wv[k] = a[lane + 32 * k];
#pragma unroll
            for (int k = 0; k < 8; k++) s += dot4(wv[k], x4[lane + 32 * k]);
        }
        {
            float4 wv[8];
#pragma unroll
            for (int k = 0; k < 8; k++) wv[k] = b[lane + 32 * k];
#pragma unroll
            for (int k = 0; k < 8; k++) s += dot4(wv[k], h4[lane + 32 * k]);
        }
        s = warp_sum(s);
        if (lane == 0) sm[2048 + gi * 8 + jj] = s + bih1[row] + bhh1[row];
        __syncthreads();

        if (tid < 8) {
            const int jo = bid * 8 + tid;
            const float ig = sigf (sm[2048 + tid]);
            const float fg = sigf (sm[2048 + 8 + tid]);
            const float gg = tanhf(sm[2048 + 16 + tid]);
            const float og = sigf (sm[2048 + 24 + tid]);
            const float c = fg * c0[H_SZ + jo] + ig * gg;
            const float h = og * tanhf(c);
            c_new[H_SZ + jo] = c;
            h_new[H_SZ + jo] = h;
            g_q[jo] = h;
        }
    }
    gbar_pf(pf_base, pf_i);

    // ============ P3: u = W^T q (+ bq) — 192 virtual blocks ======================
    for (int i = tid; i < H_SZ; i += TPB) sm[i] = g_q[i];
    __syncthreads();
    for (int vb = bid; vb < 192; vb += NBLK) {
        const int hd = vb >> 6, chunk = vb & 63;
        const float* W    = (hd == 0) ? WL : (hd == 1) ? WR : WM;
        const float* bias = (hd == 0) ? bL : (hd == 1) ? bR : bM;
        const int col = tid & 3, rgrp = tid >> 2;        // 4 f4 cols, 256 rowgroups
        const int c4 = chunk * 4 + col;
        const float4* W4 = (const float4*)W;

        float4 wv[4];
#pragma unroll
        for (int k = 0; k < 4; k++)
            wv[k] = W4[(size_t)(rgrp + 256 * k) * (C_SZ >> 2) + c4];
        float4 acc = make_float4(0.f, 0.f, 0.f, 0.f);
#pragma unroll
        for (int k = 0; k < 4; k++) {
            float qv = sm[rgrp + 256 * k];
            acc.x += wv[k].x * qv; acc.y += wv[k].y * qv;
            acc.z += wv[k].z * qv; acc.w += wv[k].w * qv;
        }
        float4* red = (float4*)(sm + H_SZ);              // 1024 float4
        red[rgrp * 4 + col] = acc;
        __syncthreads();
#pragma unroll
        for (int sd = 128; sd >= 1; sd >>= 1) {
            if (rgrp < sd) {
                float4 o = red[(rgrp + sd) * 4 + col];
                float4 m = red[rgrp * 4 + col];
                m.x += o.x; m.y += o.y; m.z += o.z; m.w += o.w;
                red[rgrp * 4 + col] = m;
            }
            __syncthreads();
        }
        if (tid < 4) ((float4*)g_u[hd])[chunk * 4 + tid] = red[tid];

        if (chunk == 0) {   // bq = bias . q, fixed-order
            float v = bias[tid] * sm[tid];
            v = warp_sum(v);
            if (lane == 0) sm[5120 + wid] = v;
            __syncthreads();
            if (tid < 32) {
                float t = sm[5120 + tid];
                t = warp_sum(t);
                if (tid == 0) g_bq[hd] = t;
            }
        }
        __syncthreads();
    }
    gbar_pf(pf_base, pf_i);

    // ============ P4: e[hd][s] = ctx[s,:]·u[hd] + bq[hd] =========================
    for (int i = tid; i < 3 * C_SZ; i += TPB) sm[i] = ((const float*)g_u)[i];
    __syncthreads();
    for (int r = gw; r < 3 * S_SZ; r += NBLK * 32) {
        const int hd = r >> 11, srow = r & (S_SZ - 1);
        const float* ctx = (hd == 0) ? ctxL : (hd == 1) ? ctxR : ctxM;
        const float4* c4 = (const float4*)(ctx + (size_t)srow * C_SZ);
        const float4* u4 = (const float4*)(sm + hd * C_SZ);
        float4 wv[8];
#pragma unroll
        for (int k = 0; k < 8; k++) wv[k] = c4[lane + 32 * k];
        float s = 0.f;
#pragma unroll
        for (int k = 0; k < 8; k++) s += dot4(wv[k], u4[lane + 32 * k]);
        s = warp_sum(s);
        if (lane == 0) g_e[hd][srow] = s + g_bq[hd];
    }
    gbar_pf(pf_base, pf_i);

    // ============ P5: softmax + weighted column-sum partials =====================
    for (int vb = bid; vb < 192; vb += NBLK) {
        const int cc = vb & 7, rc = (vb >> 3) & 7, hd = vb >> 6;
        // softmax stats over full 2048 logits (deterministic)
        const float e0 = g_e[hd][tid], e1 = g_e[hd][tid + 1024];
        float m = warp_max(fmaxf(e0, e1));
        if (lane == 0) sm[4608 + wid] = m;
        __syncthreads();
        if (tid < 32) {
            float v = sm[4608 + tid];
            v = warp_max(v);
            if (tid == 0) sm[4700] = v;
        }
        __syncthreads();
        const float M = sm[4700];
        float z = expf(e0 - M) + expf(e1 - M);
        z = warp_sum(z);
        __syncthreads();
        if (lane == 0) sm[4608 + wid] = z;
        __syncthreads();
        if (tid < 32) {
            float v = sm[4608 + tid];
            v = warp_sum(v);
            if (tid == 0) sm[4701] = v;
        }
        __syncthreads();
        const float inv = 1.0f / sm[4701];
        if (tid < 256) sm[4096 + tid] = expf(g_e[hd][rc * 256 + tid] - M) * inv;
        __syncthreads();

        // weighted column sum over 256 rows (L2-warm from P4)
        const float* ctx = (hd == 0) ? ctxL : (hd == 1) ? ctxR : ctxM;
        const float4* cp = (const float4*)ctx;
        const int c4col = cc * 32 + lane;
        float4 v[8];
#pragma unroll
        for (int k = 0; k < 8; k++)
            v[k] = cp[(size_t)(rc * 256 + wid + 32 * k) * (C_SZ >> 2) + c4col];
        float4 acc = make_float4(0.f, 0.f, 0.f, 0.f);
#pragma unroll
        for (int k = 0; k < 8; k++) {
            float av = sm[4096 + wid + 32 * k];
            acc.x += v[k].x * av; acc.y += v[k].y * av;
            acc.z += v[k].z * av; acc.w += v[k].w * av;
        }
        float4* red4 = (float4*)sm;
        red4[wid * 32 + lane] = acc;
        __syncthreads();
#pragma unroll
        for (int sd = 16; sd >= 1; sd >>= 1) {
            if (wid < sd) {
                float4 o = red4[(wid + sd) * 32 + lane];
                float4 mm = red4[wid * 32 + lane];
                mm.x += o.x; mm.y += o.y; mm.z += o.z; mm.w += o.w;
                red4[wid * 32 + lane] = mm;
            }
            __syncthreads();
        }
        if (wid == 0) ((float4*)g_wpart[hd][rc])[cc * 32 + lane] = red4[lane];
        __syncthreads();
    }
    gbar_pf(pf_base, pf_i);

    // ============ P6: concat_out = tanh(Wc @ [q|l|r|m] + bc) (blocks 0..127) =====
    if (bid < 128) {
        for (int i = tid; i < 4 * H_SZ; i += TPB) {
            float v;
            if (i < H_SZ) v = g_q[i];
            else {
                const int hd = (i >> 10) - 1;
                const int c = i & (H_SZ - 1);
                float s = 0.f;
#pragma unroll
                for (int k = 0; k < NRC; k++) s += g_wpart[hd][k][c];
                v = s;
            }
            sm[i] = v;
        }
        __syncthreads();

        const int row = bid * 8 + (wid >> 2);      // 8 rows/block, 4 warps/row
        const int seg = wid & 3;
        const float4* a  = (const float4*)(Wc + (size_t)row * 4 * H_SZ + seg * H_SZ);
        const float4* x4 = (const float4*)(sm + seg * H_SZ);
        float4 wv[8];
#pragma unroll
        for (int k = 0; k < 8; k++) wv[k] = a[lane + 32 * k];
        float s = 0.f;
#pragma unroll
        for (int k = 0; k < 8; k++) s += dot4(wv[k], x4[lane + 32 * k]);
        s = warp_sum(s);
        if (lane == 0) sm[4096 + (wid >> 2) * 4 + seg] = s;
        __syncthreads();
        if (tid < 8) {
            const float t = sm[4096 + tid * 4] + sm[4096 + tid * 4 + 1] +
                            sm[4096 + tid * 4 + 2] + sm[4096 + tid * 4 + 3];
            const int ro = bid * 8 + tid;
            g_co[ro] = tanhf(t + bc[ro]);
        }
    }
    gbar_pf(pf_base, pf_i);

    // ============ P7: output = Wo @ concat_out + bo ===============================
    if (tid < H_SZ) sm[tid] = g_co[tid];
    __syncthreads();
    const float4* x4 = (const float4*)sm;
    for (int r = gw; r < V_SZ; r += NBLK * 32) {
        const float4* a = (const float4*)(Wo + (size_t)r * H_SZ);
        float4 wv[8];
#pragma unroll
        for (int k = 0; k < 8; k++) wv[k] = a[lane + 32 * k];
        float s = 0.f;
#pragma unroll
        for (int k = 0; k < 8; k++) s += dot4(wv[k], x4[lane + 32 * k]);
        s = warp_sum(s);
        if (lane == 0) out[r] = s + bo[r];
    }
}

// ==================================================================================
extern "C" void kernel_launch(void* const* d_in, const int* in_sizes, int n_in,
                              void* d_out, int out_size) {
    const int*   input_ids = (const int*)  d_in[0];
    const float* h0        = (const float*)d_in[1];
    const float* c0        = (const float*)d_in[2];
    const float* ctxL      = (const float*)d_in[3];
    const float* ctxR      = (const float*)d_in[4];
    const float* ctxM      = (const float*)d_in[5];
    const float* emb       = (const float*)d_in[6];
    const float* Wih0      = (const float*)d_in[7];
    const float* Whh0      = (const float*)d_in[8];
    const float* bih0      = (const float*)d_in[9];
    const float* bhh0      = (const float*)d_in[10];
    const float* Wih1      = (const float*)d_in[11];
    const float* Whh1      = (const float*)d_in[12];
    const float* bih1      = (const float*)d_in[13];
    const float* bhh1      = (const float*)d_in[14];
    const float* WL        = (const float*)d_in[15];
    const float* bL        = (const float*)d_in[16];
    const float* WR        = (const float*)d_in[17];
    const float* bR        = (const float*)d_in[18];
    const float* WM        = (const float*)d_in[19];
    const float* bM        = (const float*)d_in[20];
    const float* Wc        = (const float*)d_in[21];
    const float* bc        = (const float*)d_in[22];
    const float* Wo        = (const float*)d_in[23];
    const float* bo        = (const float*)d_in[24];

    float* out   = (float*)d_out;            // [V]
    float* h_new = out + V_SZ;               // [2*H]
    float* c_new = out + V_SZ + 2 * H_SZ;    // [2*H]

    megakernel<<<NBLK, TPB>>>(input_ids, h0, c0, ctxL, ctxR, ctxM, emb,
                              Wih0, Whh0, bih0, bhh0, Wih1, Whh1, bih1, bhh1,
                              WL, bL, WR, bR, WM, bM, Wc, bc, Wo, bo,
                              out, h_new, c_new);
}